// round 8
// baseline (speedup 1.0000x reference)
#include <cuda_runtime.h>

typedef unsigned long long ull;
#define FULL 0xffffffffu
#define PI_4 0.78539816339744830962f

// ---------------- packed f32x2 helpers ----------------
__device__ __forceinline__ ull pk(float a, float b) {
    ull r; asm("mov.b64 %0, {%1,%2};" : "=l"(r) : "f"(a), "f"(b)); return r;
}
__device__ __forceinline__ void upk(ull v, float &a, float &b) {
    asm("mov.b64 {%0,%1}, %2;" : "=f"(a), "=f"(b) : "l"(v));
}
__device__ __forceinline__ ull fma2(ull a, ull b, ull c) {
    ull d; asm("fma.rn.f32x2 %0, %1, %2, %3;" : "=l"(d) : "l"(a), "l"(b), "l"(c)); return d;
}
__device__ __forceinline__ ull mul2(ull a, ull b) {
    ull d; asm("mul.rn.f32x2 %0, %1, %2;" : "=l"(d) : "l"(a), "l"(b)); return d;
}
__device__ __forceinline__ ull swp(ull v) {            // swap packed halves
    unsigned lo = (unsigned)v, hi = (unsigned)(v >> 32);
    return ((ull)lo << 32) | hi;
}

__device__ __forceinline__ float fast_tanh(float x) {
    float e = __expf(2.0f * x);
    return (e - 1.0f) / (e + 1.0f);
}

// ---------------- tan-form RY gates on packed state sp[16] ----------------
// RY(theta) = cos(t2)*(I + tan(t2)*K); cos factors folded into the amplitude
// scale, so each gate is a single FFMA2 per packed pair.
// Wire w acts on amplitude bit (9-w): wires 0..4 -> lane bits 4..0,
// wires 5..8 -> packed-index bits 3..0, wire 9 -> intra-pair.

template<int LB>
__device__ __forceinline__ void ry_lane_t(ull (&sp)[16], ull tl) {
#pragma unroll
    for (int q = 0; q < 16; q++) {
        ull p = __shfl_xor_sync(FULL, sp[q], 1 << LB);
        sp[q] = fma2(tl, p, sp[q]);
    }
}

template<int PB>
__device__ __forceinline__ void ry_local_t(ull (&sp)[16], ull pt, ull nt) {
#pragma unroll
    for (int q = 0; q < 16; q++) {
        if (!((q >> PB) & 1)) {
            ull a0 = sp[q], a1 = sp[q + (1 << PB)];
            sp[q]             = fma2(nt, a1, a0);   // a0 - t*a1
            sp[q + (1 << PB)] = fma2(pt, a0, a1);   // a1 + t*a0
        }
    }
}

__device__ __forceinline__ void ry_intra_t(ull (&sp)[16], ull mt) {
    // mt = (-t, +t): lo' = lo - t*hi, hi' = hi + t*lo
#pragma unroll
    for (int q = 0; q < 16; q++)
        sp[q] = fma2(mt, swp(sp[q]), sp[q]);
}

// ---------------- fused 9-CNOT entangling block (in-place) ----------------
// Dest-centric source: lane bits l4, l3^l4, l2^l3, l1^l2^l3, l0^l1;
// reg bits r4^(sender l0), r3^r4, r2^r3^r4, r1^r2; packed swap iff q0^q1.
// Sender-side l0 half-swap first, then the lane-uniform register permutation
// QP applied in place by cycle-following: (0)(1)(2 3)(4 6 5 7)(8 14 11 12)
// (9 15 10 13), each send optionally half-swapped by the DEST index parity.
#define RECV(v, Q) __shfl_sync(FULL, ((((Q) ^ ((Q) >> 1)) & 1) ? swp(v) : (v)), sl)

__device__ __forceinline__ void cnot_block(ull (&sp)[16], int sl, bool lx) {
#pragma unroll
    for (int q = 0; q < 8; q++) {          // pre-swap halves on l0 lanes
        ull a = sp[q], b = sp[q + 8];
        sp[q]     = lx ? b : a;
        sp[q + 8] = lx ? a : b;
    }
    ull t;
    sp[0]  = RECV(sp[0],  0);
    sp[1]  = RECV(sp[1],  1);
    t = sp[2];
    sp[2]  = RECV(sp[3],  2);  sp[3]  = RECV(t, 3);
    t = sp[4];
    sp[4]  = RECV(sp[6],  4);  sp[6]  = RECV(sp[5],  6);
    sp[5]  = RECV(sp[7],  5);  sp[7]  = RECV(t, 7);
    t = sp[8];
    sp[8]  = RECV(sp[14], 8);  sp[14] = RECV(sp[11], 14);
    sp[11] = RECV(sp[12], 11); sp[12] = RECV(t, 12);
    t = sp[9];
    sp[9]  = RECV(sp[15], 9);  sp[15] = RECV(sp[10], 15);
    sp[10] = RECV(sp[13], 10); sp[13] = RECV(t, 13);
}

// ---------------- kernel ----------------
__global__ __launch_bounds__(128, 5)
void hybrid_head_kernel(const float* __restrict__ X,       // (B,512)
                        const float* __restrict__ Wpre,    // (10,512)
                        const float* __restrict__ bpre,    // (10,)
                        const float* __restrict__ qp,      // (150,)
                        const float* __restrict__ Wpost,   // (2,10)
                        const float* __restrict__ bpost,   // (2,)
                        float* __restrict__ out,           // (B,2)
                        int B)
{
    __shared__ ull g_tp[6][10], g_tn[6][10], g_tm[6];
    __shared__ float g_cos[60];
    __shared__ float g_Cs;                    // product of the 60 shared cosines

    const int tid = threadIdx.x;
    if (tid < 60) {
        int k = tid / 10, w = tid % 10;
        float th = 0.5f * qp[(k + 1) * 10 + w];
        float c = cosf(th), t = tanf(th);
        g_tp[k][w] = pk(t, t);
        g_tn[k][w] = pk(-t, -t);
        g_cos[tid] = c;
        if (w == 9) g_tm[k] = pk(-t, t);
    }
    __syncthreads();
    if (tid == 0) {
        float prod = 1.0f;
#pragma unroll
        for (int i = 0; i < 60; i++) prod *= g_cos[i];
        g_Cs = prod;
    }
    __syncthreads();

    const int lane   = tid & 31;
    const int sample = blockIdx.x * 4 + (tid >> 5);
    if (sample >= B) return;

    // ---------------- pre-GEMM (packed accumulators) ----------------
    const float4* Xr = reinterpret_cast<const float4*>(X + (size_t)sample * 512);
    float4 xv[4];
#pragma unroll
    for (int j = 0; j < 4; j++) xv[j] = Xr[j * 32 + lane];
    ull xp[8];
#pragma unroll
    for (int j = 0; j < 4; j++) {
        xp[2 * j]     = pk(xv[j].x, xv[j].y);
        xp[2 * j + 1] = pk(xv[j].z, xv[j].w);
    }

    float acc[10];
#pragma unroll
    for (int w = 0; w < 10; w++) {
        const float4* Wr = reinterpret_cast<const float4*>(Wpre + w * 512);
        ull a2 = 0ULL;
#pragma unroll
        for (int j = 0; j < 4; j++) {
            float4 wv = Wr[j * 32 + lane];
            a2 = fma2(xp[2 * j],     pk(wv.x, wv.y), a2);
            a2 = fma2(xp[2 * j + 1], pk(wv.z, wv.w), a2);
        }
        float lo, hi; upk(a2, lo, hi);
        acc[w] = lo + hi;
    }
#pragma unroll
    for (int w = 0; w < 10; w++) {
#pragma unroll
        for (int o = 16; o > 0; o >>= 1)
            acc[w] += __shfl_xor_sync(FULL, acc[w], o);
    }

    // lane w (w<10) owns wire w's angle
    float myc, myt;
    {
        float x = acc[0] + bpre[0];
#pragma unroll
        for (int w = 1; w < 10; w++) {
            float xw = acc[w] + bpre[w];
            x = (lane == w) ? xw : x;
        }
        float th = fast_tanh(x) * PI_4;      // theta/2, |th| <= pi/4
        myc = __cosf(th);
        myt = __tanf(th);                    // |t| <= 1
    }

    // product of the 10 per-sample cosines (masked butterfly)
    float pc = (lane < 10) ? myc : 1.0f;
#pragma unroll
    for (int o = 16; o > 0; o >>= 1)
        pc *= __shfl_xor_sync(FULL, pc, o);

    const int l4 = (lane >> 4) & 1, l3 = (lane >> 3) & 1, l2 = (lane >> 2) & 1,
              l1 = (lane >> 1) & 1, l0 = lane & 1;

    // ---------------- direct product-state construction ----------------
    // amp(b) = A * prod_w (b_w ? 1+t_w : 1-t_w), A = (1/32)*prod(cos)
    ull sp[16];
    {
        float t0 = __shfl_sync(FULL, myt, 0);
        float t1 = __shfl_sync(FULL, myt, 1);
        float t2 = __shfl_sync(FULL, myt, 2);
        float t3 = __shfl_sync(FULL, myt, 3);
        float t4 = __shfl_sync(FULL, myt, 4);
        float t5 = __shfl_sync(FULL, myt, 5);
        float t6 = __shfl_sync(FULL, myt, 6);
        float t7 = __shfl_sync(FULL, myt, 7);
        float t8 = __shfl_sync(FULL, myt, 8);
        float t9 = __shfl_sync(FULL, myt, 9);

        // lane factor: wires 0..4 on lane bits 4..0
        float F = (1.0f + (l4 ? t0 : -t0));
        F *= (1.0f + (l3 ? t1 : -t1));
        F *= (1.0f + (l2 ? t2 : -t2));
        F *= (1.0f + (l1 ? t3 : -t3));
        F *= (1.0f + (l0 ? t4 : -t4));
        float FA = F * (pc * g_Cs * 0.03125f);

        // packed wire-9 pair, scaled
        ull PP = pk(FA * (1.0f - t9), FA * (1.0f + t9));

        // register tree: wires 5..8 on q bits 3..0
        float m5[2] = {1.0f - t5, 1.0f + t5};
        float m6[2] = {1.0f - t6, 1.0f + t6};
        float m7[2] = {1.0f - t7, 1.0f + t7};
        float m8[2] = {1.0f - t8, 1.0f + t8};
        float g4[4], g8[8];
#pragma unroll
        for (int i = 0; i < 4; i++) g4[i] = m5[(i >> 1) & 1] * m6[i & 1];
#pragma unroll
        for (int i = 0; i < 8; i++) g8[i] = g4[i >> 1] * m7[i & 1];
#pragma unroll
        for (int q = 0; q < 16; q++) {
            float g = g8[q >> 1] * m8[q & 1];
            sp[q] = mul2(pk(g, g), PP);
        }
    }

    // source lane of the fused CNOT permutation
    const int sl = (l4 << 4) | ((l3 ^ l4) << 3) | ((l2 ^ l3) << 2) |
                   ((l1 ^ l2 ^ l3) << 1) | (l0 ^ l1);
    const bool lx = l0;

#pragma unroll 1
    for (int k = 0; k < 6; k++) {
        cnot_block(sp, sl, lx);
        // shared RY layer k (row k+1 of q_params), tan form
        ry_lane_t<4>(sp, l4 ? g_tp[k][0] : g_tn[k][0]);
        ry_lane_t<3>(sp, l3 ? g_tp[k][1] : g_tn[k][1]);
        ry_lane_t<2>(sp, l2 ? g_tp[k][2] : g_tn[k][2]);
        ry_lane_t<1>(sp, l1 ? g_tp[k][3] : g_tn[k][3]);
        ry_lane_t<0>(sp, l0 ? g_tp[k][4] : g_tn[k][4]);
        ry_local_t<3>(sp, g_tp[k][5], g_tn[k][5]);
        ry_local_t<2>(sp, g_tp[k][6], g_tn[k][6]);
        ry_local_t<1>(sp, g_tp[k][7], g_tn[k][7]);
        ry_local_t<0>(sp, g_tp[k][8], g_tn[k][8]);
        ry_intra_t(sp, g_tm[k]);
    }

    // ---------------- <Z_w> via signed-sum tree over probs ----------------
    float s[32];
#pragma unroll
    for (int q = 0; q < 16; q++) upk(sp[q], s[2 * q], s[2 * q + 1]);

    float p[32];
#pragma unroll
    for (int r = 0; r < 32; r++) p[r] = s[r] * s[r];

    float a16[16], a8[8], a4[4], a2[2];
    float zb0 = 0.f, zb1 = 0.f, zb2 = 0.f, zb3 = 0.f;
#pragma unroll
    for (int i = 0; i < 16; i++) { a16[i] = p[2*i] + p[2*i+1]; zb0 += p[2*i] - p[2*i+1]; }
#pragma unroll
    for (int i = 0; i < 8;  i++) { a8[i]  = a16[2*i] + a16[2*i+1]; zb1 += a16[2*i] - a16[2*i+1]; }
#pragma unroll
    for (int i = 0; i < 4;  i++) { a4[i]  = a8[2*i] + a8[2*i+1];  zb2 += a8[2*i] - a8[2*i+1]; }
#pragma unroll
    for (int i = 0; i < 2;  i++) { a2[i]  = a4[2*i] + a4[2*i+1];  zb3 += a4[2*i] - a4[2*i+1]; }
    float T   = a2[0] + a2[1];
    float zb4 = a2[0] - a2[1];

    float z[10];
    z[0] = (lane & 16) ? -T : T;
    z[1] = (lane & 8)  ? -T : T;
    z[2] = (lane & 4)  ? -T : T;
    z[3] = (lane & 2)  ? -T : T;
    z[4] = (lane & 1)  ? -T : T;
    z[5] = zb4;
    z[6] = zb3;
    z[7] = zb2;
    z[8] = zb1;
    z[9] = zb0;

#pragma unroll
    for (int w = 0; w < 10; w++) {
#pragma unroll
        for (int o = 16; o > 0; o >>= 1)
            z[w] += __shfl_xor_sync(FULL, z[w], o);
    }

    // ---------------- post-GEMM ----------------
    if (lane == 0) {
        float o0 = bpost[0], o1 = bpost[1];
#pragma unroll
        for (int w = 0; w < 10; w++) {
            o0 = fmaf(z[w], Wpost[w],      o0);
            o1 = fmaf(z[w], Wpost[10 + w], o1);
        }
        reinterpret_cast<float2*>(out)[sample] = make_float2(o0, o1);
    }
}

extern "C" void kernel_launch(void* const* d_in, const int* in_sizes, int n_in,
                              void* d_out, int out_size)
{
    const float* X     = (const float*)d_in[0];
    const float* Wpre  = (const float*)d_in[1];
    const float* bpre  = (const float*)d_in[2];
    const float* qp    = (const float*)d_in[3];
    const float* Wpost = (const float*)d_in[4];
    const float* bpost = (const float*)d_in[5];
    float* out = (float*)d_out;

    int B = in_sizes[0] / 512;           // 8192
    int blocks = (B + 3) / 4;            // 4 samples (warps) per 128-thread block
    hybrid_head_kernel<<<blocks, 128>>>(X, Wpre, bpre, qp, Wpost, bpost, out, B);
}

// round 12
// speedup vs baseline: 1.0974x; 1.0974x over previous
#include <cuda_runtime.h>

typedef unsigned long long ull;
#define FULL 0xffffffffu
#define PI_4 0.78539816339744830962f

// ---------------- packed f32x2 helpers ----------------
__device__ __forceinline__ ull pk(float a, float b) {
    ull r; asm("mov.b64 %0, {%1,%2};" : "=l"(r) : "f"(a), "f"(b)); return r;
}
__device__ __forceinline__ void upk(ull v, float &a, float &b) {
    asm("mov.b64 {%0,%1}, %2;" : "=f"(a), "=f"(b) : "l"(v));
}
__device__ __forceinline__ ull fma2(ull a, ull b, ull c) {
    ull d; asm("fma.rn.f32x2 %0, %1, %2, %3;" : "=l"(d) : "l"(a), "l"(b), "l"(c)); return d;
}
__device__ __forceinline__ ull mul2(ull a, ull b) {
    ull d; asm("mul.rn.f32x2 %0, %1, %2;" : "=l"(d) : "l"(a), "l"(b)); return d;
}
__device__ __forceinline__ ull swp(ull v) {
    unsigned lo = (unsigned)v, hi = (unsigned)(v >> 32);
    return ((ull)lo << 32) | hi;
}

__device__ __forceinline__ float fast_tanh(float x) {
    float e = __expf(2.0f * x);
    return (e - 1.0f) / (e + 1.0f);
}

// ---------------- compile-time GF(2) schedule (Heisenberg CNOT elimination) ---
// Physical amplitude index bits: [9:5]=lane bits 4..0, [4:1]=reg bits q3..q0,
// [0]=packed half h. Wire w starts on bit (9-w).
// CNOTs never move data: CNOT(c,t) updates functionals phi_t ^= phi_c and
// partner masks m_c ^= m_t. RY on wire w then pairs p <-> p^m_w with sign
// parity(phi_w . p).
struct Sched {
    unsigned m[6][10];    // partner masks for RY layer k (after CNOT block k+1)
    unsigned phi[6][10];  // sign functionals; phi[5] also = measurement basis
};
__host__ __device__ constexpr Sched make_sched() {
    Sched S{};
    unsigned phi[10] = {}, m[10] = {};
    for (int w = 0; w < 10; w++) { phi[w] = 1u << (9 - w); m[w] = 1u << (9 - w); }
    const int ctl[9] = {0, 2, 4, 6, 8, 1, 3, 5, 7};   // even pairs then odd pairs
    for (int k = 0; k < 6; k++) {
        for (int g = 0; g < 9; g++) {
            int c = ctl[g], t = c + 1;
            phi[t] ^= phi[c];
            m[c]  ^= m[t];
        }
        for (int w = 0; w < 10; w++) { S.m[k][w] = m[w]; S.phi[k][w] = phi[w]; }
    }
    return S;
}
constexpr Sched SCH = make_sched();

// packed PH bits (phi[k][w]&1) for runtime use in the smem-constant init
__host__ __device__ constexpr ull make_phbits() {
    ull b = 0;
    Sched S = make_sched();
    for (int k = 0; k < 6; k++)
        for (int w = 0; w < 10; w++)
            if (S.phi[k][w] & 1) b |= 1ull << (k * 10 + w);
    return b;
}
constexpr ull PHB = make_phbits();

__host__ __device__ constexpr int topbit(int x) {
    int b = 0; while (x >> (b + 1)) b++; return 1 << b;
}

// ---------------- one RY gate in the relabeled frame ----------------
// U[0] = coeff pack for parity e=0 at h=0, U[1] = for e=1 (h=1 sign folded by PH).
template<int K, int W>
__device__ __forceinline__ void gate(ull (&sp)[16], int lane, const ull* U) {
    constexpr unsigned mm = SCH.m[K][W], pp = SCH.phi[K][W];
    constexpr int LM = (mm >> 5) & 31, RM = (mm >> 1) & 15, HM = mm & 1;
    constexpr int PL = (pp >> 5) & 31, PR = (pp >> 1) & 15;
    ull U0 = U[0], U1 = U[1];
    ull Ca, Cb;           // coeff for sigma(q)=0 / sigma(q)=1
    if constexpr (PL != 0) {
        bool f = __popc(lane & PL) & 1;
        Ca = f ? U1 : U0;
        Cb = f ? U0 : U1;
    } else { Ca = U0; Cb = U1; }

    if constexpr (LM == 0 && RM == 0) {
        // intra-pair gate (HM==1)
#pragma unroll
        for (int q = 0; q < 16; q++) {
            ull C = (__popc(q & PR) & 1) ? Cb : Ca;
            sp[q] = fma2(C, swp(sp[q]), sp[q]);
        }
    } else if constexpr (LM == 0) {
        // register-local pairs {q, q^RM}
        constexpr int hb = topbit(RM);
#pragma unroll
        for (int q = 0; q < 16; q++) {
            if (!(q & hb)) {
                const int qb = q ^ RM;
                ull a0 = sp[q], a1 = sp[qb];
                ull v0 = HM ? swp(a1) : a1;
                ull v1 = HM ? swp(a0) : a0;
                ull C0 = (__popc(q  & PR) & 1) ? Cb : Ca;
                ull C1 = (__popc(qb & PR) & 1) ? Cb : Ca;
                sp[q]  = fma2(C0, v0, a0);
                sp[qb] = fma2(C1, v1, a1);
            }
        }
    } else if constexpr (RM == 0) {
        // pure lane exchange
#pragma unroll
        for (int q = 0; q < 16; q++) {
            ull v = __shfl_xor_sync(FULL, sp[q], LM);
            if (HM) v = swp(v);
            ull C = (__popc(q & PR) & 1) ? Cb : Ca;
            sp[q] = fma2(C, v, sp[q]);
        }
    } else {
        // lane + register exchange: buffer both fetches before both writes
        constexpr int hb = topbit(RM);
#pragma unroll
        for (int q = 0; q < 16; q++) {
            if (!(q & hb)) {
                const int qb = q ^ RM;
                ull vA = __shfl_xor_sync(FULL, sp[qb], LM);
                ull vB = __shfl_xor_sync(FULL, sp[q],  LM);
                if (HM) { vA = swp(vA); vB = swp(vB); }
                ull C0 = (__popc(q  & PR) & 1) ? Cb : Ca;
                ull C1 = (__popc(qb & PR) & 1) ? Cb : Ca;
                sp[q]  = fma2(C0, vA, sp[q]);
                sp[qb] = fma2(C1, vB, sp[qb]);
            }
        }
    }
}

template<int K>
__device__ __forceinline__ void layer(ull (&sp)[16], int lane, const ull (&gU)[10][2]) {
    gate<K, 0>(sp, lane, gU[0]);
    gate<K, 1>(sp, lane, gU[1]);
    gate<K, 2>(sp, lane, gU[2]);
    gate<K, 3>(sp, lane, gU[3]);
    gate<K, 4>(sp, lane, gU[4]);
    gate<K, 5>(sp, lane, gU[5]);
    gate<K, 6>(sp, lane, gU[6]);
    gate<K, 7>(sp, lane, gU[7]);
    gate<K, 8>(sp, lane, gU[8]);
    gate<K, 9>(sp, lane, gU[9]);
}

// measurement term for wire W from the 32-point WHT F and lane parity
template<int W>
__device__ __forceinline__ float zed(const float (&F)[32], int lane) {
    constexpr unsigned pp = SCH.phi[5][W];
    constexpr int PL = (pp >> 5) & 31;
    constexpr int MR = (((pp >> 1) & 15) << 1) | (pp & 1);   // r-space mask
    float v = F[MR];
    if constexpr (PL != 0) { if (__popc(lane & PL) & 1) v = -v; }
    return v;
}

// ---------------- kernel ----------------
__global__ __launch_bounds__(128, 4)
void hybrid_head_kernel(const float* __restrict__ X,       // (B,512)
                        const float* __restrict__ Wpre,    // (10,512)
                        const float* __restrict__ bpre,    // (10,)
                        const float* __restrict__ qp,      // (150,)
                        const float* __restrict__ Wpost,   // (2,10)
                        const float* __restrict__ bpost,   // (2,)
                        float* __restrict__ out,           // (B,2)
                        int B)
{
    __shared__ ull g_U[6][10][2];
    __shared__ float g_cos[60];
    __shared__ float g_Cs;

    const int tid = threadIdx.x;
    if (tid < 60) {
        int k = tid / 10, w = tid % 10;
        float th = 0.5f * qp[(k + 1) * 10 + w];
        float c = cosf(th), t = tanf(th);
        int PH = (int)((PHB >> (k * 10 + w)) & 1ull);
        g_U[k][w][0] = pk(-t, PH ? t : -t);   // parity e=0 at h=0
        g_U[k][w][1] = pk(t, PH ? -t : t);    // parity e=1 at h=0
        g_cos[tid] = c;
    }
    __syncthreads();
    if (tid == 0) {
        float prod = 1.0f;
#pragma unroll
        for (int i = 0; i < 60; i++) prod *= g_cos[i];
        g_Cs = prod;
    }
    __syncthreads();

    const int lane   = tid & 31;
    const int sample = blockIdx.x * 4 + (tid >> 5);
    if (sample >= B) return;

    // ---------------- pre-GEMM (packed accumulators) ----------------
    const float4* Xr = reinterpret_cast<const float4*>(X + (size_t)sample * 512);
    float4 xv[4];
#pragma unroll
    for (int j = 0; j < 4; j++) xv[j] = Xr[j * 32 + lane];
    ull xp[8];
#pragma unroll
    for (int j = 0; j < 4; j++) {
        xp[2 * j]     = pk(xv[j].x, xv[j].y);
        xp[2 * j + 1] = pk(xv[j].z, xv[j].w);
    }

    float acc[10];
#pragma unroll
    for (int w = 0; w < 10; w++) {
        const float4* Wr = reinterpret_cast<const float4*>(Wpre + w * 512);
        ull a2 = 0ULL;
#pragma unroll
        for (int j = 0; j < 4; j++) {
            float4 wv = Wr[j * 32 + lane];
            a2 = fma2(xp[2 * j],     pk(wv.x, wv.y), a2);
            a2 = fma2(xp[2 * j + 1], pk(wv.z, wv.w), a2);
        }
        float lo, hi; upk(a2, lo, hi);
        acc[w] = lo + hi;
    }
#pragma unroll
    for (int w = 0; w < 10; w++) {
#pragma unroll
        for (int o = 16; o > 0; o >>= 1)
            acc[w] += __shfl_xor_sync(FULL, acc[w], o);
    }

    // lane w (w<10) owns wire w's angle
    float myc, myt;
    {
        float x = acc[0] + bpre[0];
#pragma unroll
        for (int w = 1; w < 10; w++) {
            float xw = acc[w] + bpre[w];
            x = (lane == w) ? xw : x;
        }
        float th = fast_tanh(x) * PI_4;      // theta/2, |th| <= pi/4
        myc = __cosf(th);
        myt = __tanf(th);                    // |t| <= 1
    }

    // product of the 10 per-sample cosines (masked butterfly)
    float pc = (lane < 10) ? myc : 1.0f;
#pragma unroll
    for (int o = 16; o > 0; o >>= 1)
        pc *= __shfl_xor_sync(FULL, pc, o);

    const int l4 = (lane >> 4) & 1, l3 = (lane >> 3) & 1, l2 = (lane >> 2) & 1,
              l1 = (lane >> 1) & 1, l0 = lane & 1;

    // ---------------- direct product-state construction ----------------
    // amp(b) = A * prod_w (b_w ? 1+t_w : 1-t_w), A = (1/32)*prod(cos)
    ull sp[16];
    {
        float t0 = __shfl_sync(FULL, myt, 0);
        float t1 = __shfl_sync(FULL, myt, 1);
        float t2 = __shfl_sync(FULL, myt, 2);
        float t3 = __shfl_sync(FULL, myt, 3);
        float t4 = __shfl_sync(FULL, myt, 4);
        float t5 = __shfl_sync(FULL, myt, 5);
        float t6 = __shfl_sync(FULL, myt, 6);
        float t7 = __shfl_sync(FULL, myt, 7);
        float t8 = __shfl_sync(FULL, myt, 8);
        float t9 = __shfl_sync(FULL, myt, 9);

        float F = (1.0f + (l4 ? t0 : -t0));
        F *= (1.0f + (l3 ? t1 : -t1));
        F *= (1.0f + (l2 ? t2 : -t2));
        F *= (1.0f + (l1 ? t3 : -t3));
        F *= (1.0f + (l0 ? t4 : -t4));
        float FA = F * (pc * g_Cs * 0.03125f);

        ull PP = pk(FA * (1.0f - t9), FA * (1.0f + t9));

        float m5[2] = {1.0f - t5, 1.0f + t5};
        float m6[2] = {1.0f - t6, 1.0f + t6};
        float m7[2] = {1.0f - t7, 1.0f + t7};
        float m8[2] = {1.0f - t8, 1.0f + t8};
        float g4[4], g8[8];
#pragma unroll
        for (int i = 0; i < 4; i++) g4[i] = m5[(i >> 1) & 1] * m6[i & 1];
#pragma unroll
        for (int i = 0; i < 8; i++) g8[i] = g4[i >> 1] * m7[i & 1];
#pragma unroll
        for (int q = 0; q < 16; q++) {
            float g = g8[q >> 1] * m8[q & 1];
            sp[q] = mul2(pk(g, g), PP);
        }
    }

    // ---------------- 6 entangling+RY layers (CNOTs are free relabelings) ----
    layer<0>(sp, lane, g_U[0]);
    layer<1>(sp, lane, g_U[1]);
    layer<2>(sp, lane, g_U[2]);
    layer<3>(sp, lane, g_U[3]);
    layer<4>(sp, lane, g_U[4]);
    layer<5>(sp, lane, g_U[5]);

    // ---------------- measurement: probs -> 32-pt WHT -> z via final phi -----
    float F[32];
#pragma unroll
    for (int q = 0; q < 16; q++) {
        float lo, hi; upk(sp[q], lo, hi);
        F[2 * q]     = lo * lo;
        F[2 * q + 1] = hi * hi;
    }
#pragma unroll
    for (int b = 0; b < 5; b++) {
        const int mk = 1 << b;
#pragma unroll
        for (int r = 0; r < 32; r++) {
            if (!(r & mk)) {
                float a = F[r], c = F[r | mk];
                F[r]      = a + c;
                F[r | mk] = a - c;
            }
        }
    }

    float z[10];
    z[0] = zed<0>(F, lane);
    z[1] = zed<1>(F, lane);
    z[2] = zed<2>(F, lane);
    z[3] = zed<3>(F, lane);
    z[4] = zed<4>(F, lane);
    z[5] = zed<5>(F, lane);
    z[6] = zed<6>(F, lane);
    z[7] = zed<7>(F, lane);
    z[8] = zed<8>(F, lane);
    z[9] = zed<9>(F, lane);

#pragma unroll
    for (int w = 0; w < 10; w++) {
#pragma unroll
        for (int o = 16; o > 0; o >>= 1)
            z[w] += __shfl_xor_sync(FULL, z[w], o);
    }

    // ---------------- post-GEMM ----------------
    if (lane == 0) {
        float o0 = bpost[0], o1 = bpost[1];
#pragma unroll
        for (int w = 0; w < 10; w++) {
            o0 = fmaf(z[w], Wpost[w],      o0);
            o1 = fmaf(z[w], Wpost[10 + w], o1);
        }
        reinterpret_cast<float2*>(out)[sample] = make_float2(o0, o1);
    }
}

extern "C" void kernel_launch(void* const* d_in, const int* in_sizes, int n_in,
                              void* d_out, int out_size)
{
    const float* X     = (const float*)d_in[0];
    const float* Wpre  = (const float*)d_in[1];
    const float* bpre  = (const float*)d_in[2];
    const float* qp    = (const float*)d_in[3];
    const float* Wpost = (const float*)d_in[4];
    const float* bpost = (const float*)d_in[5];
    float* out = (float*)d_out;

    int B = in_sizes[0] / 512;           // 8192
    int blocks = (B + 3) / 4;            // 4 samples (warps) per 128-thread block
    hybrid_head_kernel<<<blocks, 128>>>(X, Wpre, bpre, qp, Wpost, bpost, out, B);
}

// round 13
// speedup vs baseline: 1.1490x; 1.0471x over previous
#include <cuda_runtime.h>

typedef unsigned long long ull;
#define FULL 0xffffffffu
#define PI_4 0.78539816339744830962f
#define SGN2 0x8000000080000000ULL

// ---------------- packed f32x2 helpers ----------------
__device__ __forceinline__ ull pk(float a, float b) {
    ull r; asm("mov.b64 %0, {%1,%2};" : "=l"(r) : "f"(a), "f"(b)); return r;
}
__device__ __forceinline__ void upk(ull v, float &a, float &b) {
    asm("mov.b64 {%0,%1}, %2;" : "=f"(a), "=f"(b) : "l"(v));
}
__device__ __forceinline__ ull fma2(ull a, ull b, ull c) {
    ull d; asm("fma.rn.f32x2 %0, %1, %2, %3;" : "=l"(d) : "l"(a), "l"(b), "l"(c)); return d;
}
__device__ __forceinline__ ull mul2(ull a, ull b) {
    ull d; asm("mul.rn.f32x2 %0, %1, %2;" : "=l"(d) : "l"(a), "l"(b)); return d;
}
__device__ __forceinline__ ull swp(ull v) {
    unsigned lo = (unsigned)v, hi = (unsigned)(v >> 32);
    return ((ull)lo << 32) | hi;
}

__device__ __forceinline__ float fast_tanh(float x) {
    float e = __expf(2.0f * x);
    return (e - 1.0f) / (e + 1.0f);
}

// ---------------- compile-time GF(2) schedule (Heisenberg CNOT elimination) ---
// Physical amplitude index bits: [9:5]=lane bits 4..0, [4:1]=reg bits q3..q0,
// [0]=packed half h. Wire w starts on bit (9-w).
// CNOTs never move data: CNOT(c,t) updates functionals phi_t ^= phi_c and
// partner masks m_c ^= m_t. RY on wire w then pairs p <-> p^m_w with sign
// parity(phi_w . p).
struct Sched {
    unsigned m[6][10];
    unsigned phi[6][10];
};
__host__ __device__ constexpr Sched make_sched() {
    Sched S{};
    unsigned phi[10] = {}, m[10] = {};
    for (int w = 0; w < 10; w++) { phi[w] = 1u << (9 - w); m[w] = 1u << (9 - w); }
    const int ctl[9] = {0, 2, 4, 6, 8, 1, 3, 5, 7};
    for (int k = 0; k < 6; k++) {
        for (int g = 0; g < 9; g++) {
            int c = ctl[g], t = c + 1;
            phi[t] ^= phi[c];
            m[c]  ^= m[t];
        }
        for (int w = 0; w < 10; w++) { S.m[k][w] = m[w]; S.phi[k][w] = phi[w]; }
    }
    return S;
}
constexpr Sched SCH = make_sched();

__host__ __device__ constexpr ull make_phbits() {
    ull b = 0;
    Sched S = make_sched();
    for (int k = 0; k < 6; k++)
        for (int w = 0; w < 10; w++)
            if (S.phi[k][w] & 1) b |= 1ull << (k * 10 + w);
    return b;
}
constexpr ull PHB = make_phbits();

__host__ __device__ constexpr int topbit(int x) {
    int b = 0; while (x >> (b + 1)) b++; return 1 << b;
}

// ---------------- one RY gate in the relabeled frame ----------------
// U0 = coeff pack for parity e=0 at h=0; the e=1 pack is exactly -U0.
template<int K, int W>
__device__ __forceinline__ void gate(ull (&sp)[16], int lane, ull U0) {
    constexpr unsigned mm = SCH.m[K][W], pp = SCH.phi[K][W];
    constexpr int LM = (mm >> 5) & 31, RM = (mm >> 1) & 15, HM = mm & 1;
    constexpr int PL = (pp >> 5) & 31, PR = (pp >> 1) & 15;
    ull n0 = U0 ^ SGN2;    // = U1 (componentwise negation)
    ull Ca, Cb;            // coeff for sigma(q)=0 / sigma(q)=1
    if constexpr (PL != 0) {
        bool f = __popc(lane & PL) & 1;
        Ca = f ? n0 : U0;
        Cb = f ? U0 : n0;
    } else { Ca = U0; Cb = n0; }

    if constexpr (LM == 0 && RM == 0) {
#pragma unroll
        for (int q = 0; q < 16; q++) {
            ull C = (__popc(q & PR) & 1) ? Cb : Ca;
            sp[q] = fma2(C, swp(sp[q]), sp[q]);
        }
    } else if constexpr (LM == 0) {
        constexpr int hb = topbit(RM);
#pragma unroll
        for (int q = 0; q < 16; q++) {
            if (!(q & hb)) {
                const int qb = q ^ RM;
                ull a0 = sp[q], a1 = sp[qb];
                ull v0 = HM ? swp(a1) : a1;
                ull v1 = HM ? swp(a0) : a0;
                ull C0 = (__popc(q  & PR) & 1) ? Cb : Ca;
                ull C1 = (__popc(qb & PR) & 1) ? Cb : Ca;
                sp[q]  = fma2(C0, v0, a0);
                sp[qb] = fma2(C1, v1, a1);
            }
        }
    } else if constexpr (RM == 0) {
#pragma unroll
        for (int q = 0; q < 16; q++) {
            ull v = __shfl_xor_sync(FULL, sp[q], LM);
            if (HM) v = swp(v);
            ull C = (__popc(q & PR) & 1) ? Cb : Ca;
            sp[q] = fma2(C, v, sp[q]);
        }
    } else {
        constexpr int hb = topbit(RM);
#pragma unroll
        for (int q = 0; q < 16; q++) {
            if (!(q & hb)) {
                const int qb = q ^ RM;
                ull vA = __shfl_xor_sync(FULL, sp[qb], LM);
                ull vB = __shfl_xor_sync(FULL, sp[q],  LM);
                if (HM) { vA = swp(vA); vB = swp(vB); }
                ull C0 = (__popc(q  & PR) & 1) ? Cb : Ca;
                ull C1 = (__popc(qb & PR) & 1) ? Cb : Ca;
                sp[q]  = fma2(C0, vA, sp[q]);
                sp[qb] = fma2(C1, vB, sp[qb]);
            }
        }
    }
}

template<int K>
__device__ __forceinline__ void layer(ull (&sp)[16], int lane, const ull (&gU)[10]) {
    gate<K, 0>(sp, lane, gU[0]);
    gate<K, 1>(sp, lane, gU[1]);
    gate<K, 2>(sp, lane, gU[2]);
    gate<K, 3>(sp, lane, gU[3]);
    gate<K, 4>(sp, lane, gU[4]);
    gate<K, 5>(sp, lane, gU[5]);
    gate<K, 6>(sp, lane, gU[6]);
    gate<K, 7>(sp, lane, gU[7]);
    gate<K, 8>(sp, lane, gU[8]);
    gate<K, 9>(sp, lane, gU[9]);
}

// measurement term for wire W from the 32-point WHT F and lane parity
template<int W>
__device__ __forceinline__ float zed(const float (&F)[32], int lane) {
    constexpr unsigned pp = SCH.phi[5][W];
    constexpr int PL = (pp >> 5) & 31;
    constexpr int MR = (((pp >> 1) & 15) << 1) | (pp & 1);
    float v = F[MR];
    if constexpr (PL != 0) { if (__popc(lane & PL) & 1) v = -v; }
    return v;
}

// ---------------- kernel ----------------
__global__ __launch_bounds__(128, 5)
void hybrid_head_kernel(const float* __restrict__ X,       // (B,512)
                        const float* __restrict__ Wpre,    // (10,512)
                        const float* __restrict__ bpre,    // (10,)
                        const float* __restrict__ qp,      // (150,)
                        const float* __restrict__ Wpost,   // (2,10)
                        const float* __restrict__ bpost,   // (2,)
                        float* __restrict__ out,           // (B,2)
                        int B)
{
    __shared__ ull g_U[6][10];
    __shared__ float g_cos[60];
    __shared__ float g_Cs;

    const int tid = threadIdx.x;
    if (tid < 60) {
        int k = tid / 10, w = tid % 10;
        float th = 0.5f * qp[(k + 1) * 10 + w];
        float c = cosf(th), t = tanf(th);
        int PH = (int)((PHB >> (k * 10 + w)) & 1ull);
        g_U[k][w] = pk(-t, PH ? t : -t);   // parity e=0 pack; e=1 = negation
        g_cos[tid] = c;
    }
    __syncthreads();
    if (tid == 0) {
        float prod = 1.0f;
#pragma unroll
        for (int i = 0; i < 60; i++) prod *= g_cos[i];
        g_Cs = prod;
    }
    __syncthreads();

    const int lane   = tid & 31;
    const int sample = blockIdx.x * 4 + (tid >> 5);
    if (sample >= B) return;

    // ---------------- pre-GEMM (packed accumulators) ----------------
    const float4* Xr = reinterpret_cast<const float4*>(X + (size_t)sample * 512);
    float4 xv[4];
#pragma unroll
    for (int j = 0; j < 4; j++) xv[j] = Xr[j * 32 + lane];
    ull xp[8];
#pragma unroll
    for (int j = 0; j < 4; j++) {
        xp[2 * j]     = pk(xv[j].x, xv[j].y);
        xp[2 * j + 1] = pk(xv[j].z, xv[j].w);
    }

    float acc[10];
#pragma unroll
    for (int w = 0; w < 10; w++) {
        const float4* Wr = reinterpret_cast<const float4*>(Wpre + w * 512);
        ull a2 = 0ULL;
#pragma unroll
        for (int j = 0; j < 4; j++) {
            float4 wv = Wr[j * 32 + lane];
            a2 = fma2(xp[2 * j],     pk(wv.x, wv.y), a2);
            a2 = fma2(xp[2 * j + 1], pk(wv.z, wv.w), a2);
        }
        float lo, hi; upk(a2, lo, hi);
        acc[w] = lo + hi;
    }
#pragma unroll
    for (int w = 0; w < 10; w++) {
#pragma unroll
        for (int o = 16; o > 0; o >>= 1)
            acc[w] += __shfl_xor_sync(FULL, acc[w], o);
    }

    // lane w (w<10) owns wire w's angle
    float myc, myt;
    {
        float x = acc[0] + bpre[0];
#pragma unroll
        for (int w = 1; w < 10; w++) {
            float xw = acc[w] + bpre[w];
            x = (lane == w) ? xw : x;
        }
        float th = fast_tanh(x) * PI_4;      // theta/2, |th| <= pi/4
        myc = __cosf(th);
        myt = __tanf(th);                    // |t| <= 1
    }

    // product of the 10 per-sample cosines (masked butterfly)
    float pc = (lane < 10) ? myc : 1.0f;
#pragma unroll
    for (int o = 16; o > 0; o >>= 1)
        pc *= __shfl_xor_sync(FULL, pc, o);

    const int l4 = (lane >> 4) & 1, l3 = (lane >> 3) & 1, l2 = (lane >> 2) & 1,
              l1 = (lane >> 1) & 1, l0 = lane & 1;

    // ---------------- direct product-state construction ----------------
    // amp(b) = A * prod_w (b_w ? 1+t_w : 1-t_w), A = (1/32)*prod(cos)
    ull sp[16];
    {
        float t0 = __shfl_sync(FULL, myt, 0);
        float t1 = __shfl_sync(FULL, myt, 1);
        float t2 = __shfl_sync(FULL, myt, 2);
        float t3 = __shfl_sync(FULL, myt, 3);
        float t4 = __shfl_sync(FULL, myt, 4);
        float t5 = __shfl_sync(FULL, myt, 5);
        float t6 = __shfl_sync(FULL, myt, 6);
        float t7 = __shfl_sync(FULL, myt, 7);
        float t8 = __shfl_sync(FULL, myt, 8);
        float t9 = __shfl_sync(FULL, myt, 9);

        float F = (1.0f + (l4 ? t0 : -t0));
        F *= (1.0f + (l3 ? t1 : -t1));
        F *= (1.0f + (l2 ? t2 : -t2));
        F *= (1.0f + (l1 ? t3 : -t3));
        F *= (1.0f + (l0 ? t4 : -t4));
        float FA = F * (pc * g_Cs * 0.03125f);

        ull PP = pk(FA * (1.0f - t9), FA * (1.0f + t9));

        float m5[2] = {1.0f - t5, 1.0f + t5};
        float m6[2] = {1.0f - t6, 1.0f + t6};
        float m7[2] = {1.0f - t7, 1.0f + t7};
        float m8[2] = {1.0f - t8, 1.0f + t8};
        float g4[4], g8[8];
#pragma unroll
        for (int i = 0; i < 4; i++) g4[i] = m5[(i >> 1) & 1] * m6[i & 1];
#pragma unroll
        for (int i = 0; i < 8; i++) g8[i] = g4[i >> 1] * m7[i & 1];
#pragma unroll
        for (int q = 0; q < 16; q++) {
            float g = g8[q >> 1] * m8[q & 1];
            sp[q] = mul2(pk(g, g), PP);
        }
    }

    // ---------------- 6 entangling+RY layers (CNOTs are free relabelings) ----
    layer<0>(sp, lane, g_U[0]);
    layer<1>(sp, lane, g_U[1]);
    layer<2>(sp, lane, g_U[2]);
    layer<3>(sp, lane, g_U[3]);
    layer<4>(sp, lane, g_U[4]);
    layer<5>(sp, lane, g_U[5]);

    // ---------------- measurement: probs -> 32-pt WHT -> z via final phi -----
    float F[32];
#pragma unroll
    for (int q = 0; q < 16; q++) {
        float lo, hi; upk(sp[q], lo, hi);
        F[2 * q]     = lo * lo;
        F[2 * q + 1] = hi * hi;
    }
#pragma unroll
    for (int b = 0; b < 5; b++) {
        const int mk = 1 << b;
#pragma unroll
        for (int r = 0; r < 32; r++) {
            if (!(r & mk)) {
                float a = F[r], c = F[r | mk];
                F[r]      = a + c;
                F[r | mk] = a - c;
            }
        }
    }

    float z[10];
    z[0] = zed<0>(F, lane);
    z[1] = zed<1>(F, lane);
    z[2] = zed<2>(F, lane);
    z[3] = zed<3>(F, lane);
    z[4] = zed<4>(F, lane);
    z[5] = zed<5>(F, lane);
    z[6] = zed<6>(F, lane);
    z[7] = zed<7>(F, lane);
    z[8] = zed<8>(F, lane);
    z[9] = zed<9>(F, lane);

#pragma unroll
    for (int w = 0; w < 10; w++) {
#pragma unroll
        for (int o = 16; o > 0; o >>= 1)
            z[w] += __shfl_xor_sync(FULL, z[w], o);
    }

    // ---------------- post-GEMM ----------------
    if (lane == 0) {
        float o0 = bpost[0], o1 = bpost[1];
#pragma unroll
        for (int w = 0; w < 10; w++) {
            o0 = fmaf(z[w], Wpost[w],      o0);
            o1 = fmaf(z[w], Wpost[10 + w], o1);
        }
        reinterpret_cast<float2*>(out)[sample] = make_float2(o0, o1);
    }
}

extern "C" void kernel_launch(void* const* d_in, const int* in_sizes, int n_in,
                              void* d_out, int out_size)
{
    const float* X     = (const float*)d_in[0];
    const float* Wpre  = (const float*)d_in[1];
    const float* bpre  = (const float*)d_in[2];
    const float* qp    = (const float*)d_in[3];
    const float* Wpost = (const float*)d_in[4];
    const float* bpost = (const float*)d_in[5];
    float* out = (float*)d_out;

    int B = in_sizes[0] / 512;           // 8192
    int blocks = (B + 3) / 4;            // 4 samples (warps) per 128-thread block
    hybrid_head_kernel<<<blocks, 128>>>(X, Wpre, bpre, qp, Wpost, bpost, out, B);
}